// round 8
// baseline (speedup 1.0000x reference)
#include <cuda_runtime.h>
#include <math.h>

// Problem constants
constexpr int N_NODES = 50000;
constexpr int F_IN    = 128;
constexpr int E_EDGES = 800000;
constexpr int DIM     = 64;
constexpr int G_GRAPH = 128;
constexpr int C_CLS   = 10;
constexpr float BN_EPS = 1e-5f;

// ----------------------------------------------------------------------------
// Device-global scratch (referenced ONLY from device code)
// ----------------------------------------------------------------------------
__device__ float g_agg[N_NODES * DIM];
__device__ float g_u[N_NODES * DIM];
__device__ float g_h[N_NODES * DIM];
__device__ float g_sum[DIM];
__device__ float g_sumsq[DIM];
__device__ float g_scale[DIM];
__device__ float g_shift[DIM];
__device__ float g_Wp[DIM * DIM];          // diag(scale) @ Wa_next
__device__ float g_cvec[DIM];              // shift @ Wa_next
__device__ int   g_deg[N_NODES];
__device__ int   g_gcnt[G_GRAPH];
__device__ int   g_rowstart[N_NODES + 1];
__device__ int   g_cursor[N_NODES];
__device__ int   g_csr[E_EDGES];
__device__ float g_pooled[G_GRAPH * DIM];

enum { BUF_U = 1, BUF_H = 2 };
__device__ __forceinline__ const float* get_buf(int id) {
    return id == BUF_U ? g_u : g_h;
}

__device__ __forceinline__ void red_v4(float* p, float4 v) {
    asm volatile("red.global.add.v4.f32 [%0], {%1,%2,%3,%4};"
                 :: "l"(p), "f"(v.x), "f"(v.y), "f"(v.z), "f"(v.w) : "memory");
}

// f32x2 packed-math helpers
__device__ __forceinline__ unsigned long long pack2(float x) {
    unsigned long long r;
    asm("mov.b64 %0, {%1, %1};" : "=l"(r) : "r"(__float_as_uint(x)));
    return r;
}
__device__ __forceinline__ void ffma2(unsigned long long& d,
                                      unsigned long long a, unsigned long long b) {
    asm("fma.rn.f32x2 %0, %1, %2, %0;" : "+l"(d) : "l"(a), "l"(b));
}
__device__ __forceinline__ void unpack2(unsigned long long v, float& lo, float& hi) {
    unsigned int a, b;
    asm("mov.b64 {%0, %1}, %2;" : "=r"(a), "=r"(b) : "l"(v));
    lo = __uint_as_float(a);
    hi = __uint_as_float(b);
}

// ----------------------------------------------------------------------------
// Init + CSR build
// ----------------------------------------------------------------------------
__global__ void init_kernel() {
    int t = blockIdx.x * blockDim.x + threadIdx.x;
    if (t < N_NODES) g_deg[t] = 0;
    if (t < G_GRAPH) g_gcnt[t] = 0;
    if (t < DIM) { g_sum[t] = 0.f; g_sumsq[t] = 0.f; }
    if (t < G_GRAPH * DIM) g_pooled[t] = 0.f;
}

__global__ void counts_kernel(const int* __restrict__ ei,
                              const int* __restrict__ batch) {
    int t = blockIdx.x * blockDim.x + threadIdx.x;
    if (t < E_EDGES) atomicAdd(&g_deg[ei[E_EDGES + t]], 1);
    if (t < N_NODES) atomicAdd(&g_gcnt[batch[t]], 1);
}

__global__ void scan_kernel() {
    constexpr int CH = (N_NODES + 1023) / 1024;  // 49
    int tid = threadIdx.x;
    int start = tid * CH;
    int s = 0;
    for (int i = 0; i < CH; i++) {
        int idx = start + i;
        if (idx < N_NODES) s += g_deg[idx];
    }
    __shared__ int ps[1024];
    ps[tid] = s;
    __syncthreads();
    for (int off = 1; off < 1024; off <<= 1) {
        int add = (tid >= off) ? ps[tid - off] : 0;
        __syncthreads();
        ps[tid] += add;
        __syncthreads();
    }
    int run = ps[tid] - s;   // exclusive base
    for (int i = 0; i < CH; i++) {
        int idx = start + i;
        if (idx < N_NODES) {
            g_rowstart[idx] = run;
            g_cursor[idx]   = run;
            run += g_deg[idx];
        }
    }
    if (tid == 0) g_rowstart[N_NODES] = E_EDGES;
}

__global__ void place_kernel(const int* __restrict__ ei) {
    int t = blockIdx.x * blockDim.x + threadIdx.x;
    if (t >= E_EDGES) return;
    int dst = ei[E_EDGES + t];
    int pos = atomicAdd(&g_cursor[dst], 1);
    g_csr[pos] = ei[t];
}

// ----------------------------------------------------------------------------
// Per-layer small kernels
// ----------------------------------------------------------------------------
__global__ void bn_params_kernel(const float* __restrict__ gamma,
                                 const float* __restrict__ beta) {
    int j = threadIdx.x;
    if (j >= DIM) return;
    const float inv_n = 1.0f / (float)N_NODES;
    float su = g_sum[j], sq = g_sumsq[j];
    float mean = su * inv_n;
    float var  = sq * inv_n - mean * mean;
    float rstd = rsqrtf(var + BN_EPS);
    float sc = gamma[j] * rstd;
    g_scale[j] = sc;
    g_shift[j] = beta[j] - mean * sc;
    g_sum[j] = 0.f;
    g_sumsq[j] = 0.f;
}

__global__ void fold_kernel(const float* __restrict__ Wa) {
    int tid = threadIdx.x;   // one block of 256
    for (int i = tid; i < DIM * DIM; i += 256)
        g_Wp[i] = g_scale[i >> 6] * Wa[i];
    if (tid < DIM) {
        float c = 0.f;
        for (int k = 0; k < DIM; k++) c = fmaf(g_shift[k], Wa[k * DIM + tid], c);
        g_cvec[tid] = c;
    }
}

// ----------------------------------------------------------------------------
// CSR gather: g_agg[n] = buf[n] + sum_{nbr} buf[nbr].  Half-warp per node.
// ----------------------------------------------------------------------------
template <int SRC>
__global__ void gather_kernel() {
    int t = blockIdx.x * blockDim.x + threadIdx.x;
    int node = t >> 4;
    int c = t & 15;
    if (node >= N_NODES) return;
    const float4* sp = (const float4*)get_buf(SRC);
    float4 acc = sp[node * 16 + c];
    int s = g_rowstart[node];
    int e = g_rowstart[node + 1];
#pragma unroll 4
    for (int j = s; j < e; j++) {
        int src = __ldg(&g_csr[j]);
        float4 v = sp[src * 16 + c];
        acc.x += v.x; acc.y += v.y; acc.z += v.z; acc.w += v.w;
    }
    ((float4*)g_agg)[node * 16 + c] = acc;
}

// ----------------------------------------------------------------------------
// f32x2 register-tiled GEMM core.
// 256 threads = 64 row-threads x 4 col-groups; thread tile 4 rows x 16 cols.
// MODE: 0 = bias+relu out (d), 1 = input bias+relu, bias+relu out (l1b),
//       2 = deg*cvec + bias + relu out (c), 3 = plain, no bias/relu (xw)
// STATS: accumulate column sum/sumsq of output into g_sum/g_sumsq.
// POOL:  red.v4 output into g_pooled[batch[row]].
// ----------------------------------------------------------------------------
template <int K, int MODE, bool STATS, bool POOL>
__device__ __forceinline__ void gemm_core(const float* __restrict__ in,
                                          const float* __restrict__ Wsrc,
                                          const float* __restrict__ bin,
                                          const float* __restrict__ bout,
                                          float* __restrict__ out,
                                          const int* __restrict__ batch) {
    __shared__ float ws[K * DIM];
    __shared__ float bi_s[DIM], bo_s[DIM], cv_s[DIM];
    __shared__ float red_s[STATS ? DIM * 65 : 1];

    int tid = threadIdx.x;
    for (int i = tid; i < K * DIM; i += 256) ws[i] = Wsrc[i];
    if (tid < DIM) {
        bo_s[tid] = (MODE == 3) ? 0.f : bout[tid];
        if (MODE == 1) bi_s[tid] = bin[tid];
        if (MODE == 2) cv_s[tid] = g_cvec[tid];
    }
    __syncthreads();

    int cg = tid & 3;                 // column group (16 cols)
    int rt = tid >> 2;                // row thread
    int row0 = blockIdx.x * 256 + rt * 4;
    int colbase = cg * 16;

    unsigned long long acc2[4][8];
#pragma unroll
    for (int i = 0; i < 4; i++)
#pragma unroll
        for (int p = 0; p < 8; p++) acc2[i][p] = 0ULL;

    bool v[4];
#pragma unroll
    for (int i = 0; i < 4; i++) v[i] = (row0 + i) < N_NODES;

    const float4* in4 = (const float4*)in;
    const float4 z4 = make_float4(0.f, 0.f, 0.f, 0.f);

#pragma unroll 2
    for (int k4 = 0; k4 < K / 4; k4++) {
        float4 a[4];
#pragma unroll
        for (int i = 0; i < 4; i++)
            a[i] = v[i] ? in4[(row0 + i) * (K / 4) + k4] : z4;
        if (MODE == 1) {
            float4 b = ((const float4*)bi_s)[k4];
#pragma unroll
            for (int i = 0; i < 4; i++) {
                a[i].x = fmaxf(a[i].x + b.x, 0.f);
                a[i].y = fmaxf(a[i].y + b.y, 0.f);
                a[i].z = fmaxf(a[i].z + b.z, 0.f);
                a[i].w = fmaxf(a[i].w + b.w, 0.f);
            }
        }
#pragma unroll
        for (int kk = 0; kk < 4; kk++) {
            const ulonglong2* wr =
                (const ulonglong2*)&ws[(k4 * 4 + kk) * DIM + colbase];
            ulonglong2 w01 = wr[0];
            ulonglong2 w23 = wr[1];
            ulonglong2 w45 = wr[2];
            ulonglong2 w67 = wr[3];
#pragma unroll
            for (int i = 0; i < 4; i++) {
                const float* ap = (const float*)&a[i];
                unsigned long long e2 = pack2(ap[kk]);
                ffma2(acc2[i][0], e2, w01.x);
                ffma2(acc2[i][1], e2, w01.y);
                ffma2(acc2[i][2], e2, w23.x);
                ffma2(acc2[i][3], e2, w23.y);
                ffma2(acc2[i][4], e2, w45.x);
                ffma2(acc2[i][5], e2, w45.y);
                ffma2(acc2[i][6], e2, w67.x);
                ffma2(acc2[i][7], e2, w67.y);
            }
        }
    }

    float colsum[16], colsumsq[16];
    if (STATS) {
#pragma unroll
        for (int c = 0; c < 16; c++) { colsum[c] = 0.f; colsumsq[c] = 0.f; }
    }

    float4* o4 = (float4*)out;
#pragma unroll
    for (int i = 0; i < 4; i++) {
        if (!v[i]) continue;
        float r[16];
#pragma unroll
        for (int p = 0; p < 8; p++) unpack2(acc2[i][p], r[2 * p], r[2 * p + 1]);

        if (MODE == 2) {
            float dp1 = 1.0f + (float)g_deg[row0 + i];
#pragma unroll
            for (int c = 0; c < 16; c++)
                r[c] = fmaxf(fmaf(dp1, cv_s[colbase + c], r[c]) + bo_s[colbase + c], 0.f);
        } else if (MODE != 3) {
#pragma unroll
            for (int c = 0; c < 16; c++)
                r[c] = fmaxf(r[c] + bo_s[colbase + c], 0.f);
        }

        if (STATS) {
#pragma unroll
            for (int c = 0; c < 16; c++) {
                colsum[c] += r[c];
                colsumsq[c] = fmaf(r[c], r[c], colsumsq[c]);
            }
        }

        int gb = 0;
        if (POOL) gb = batch[row0 + i];

#pragma unroll
        for (int c4 = 0; c4 < 4; c4++) {
            float4 w = make_float4(r[4*c4+0], r[4*c4+1], r[4*c4+2], r[4*c4+3]);
            o4[(row0 + i) * 16 + cg * 4 + c4] = w;
            if (POOL) red_v4(g_pooled + gb * DIM + colbase + c4 * 4, w);
        }
    }

    if (STATS) {
        // Pass 1: column sums
#pragma unroll
        for (int c = 0; c < 16; c++) red_s[(colbase + c) * 65 + rt] = colsum[c];
        __syncthreads();
        if (tid < DIM) {
            float s = 0.f;
            for (int k = 0; k < 64; k++) s += red_s[tid * 65 + ((tid + k) & 63)];
            atomicAdd(&g_sum[tid], s);
        }
        __syncthreads();
        // Pass 2: column sums of squares (reuse buffer)
#pragma unroll
        for (int c = 0; c < 16; c++) red_s[(colbase + c) * 65 + rt] = colsumsq[c];
        __syncthreads();
        if (tid < DIM) {
            float s = 0.f;
            for (int k = 0; k < 64; k++) s += red_s[tid * 65 + ((tid + k) & 63)];
            atomicAdd(&g_sumsq[tid], s);
        }
    }
}

// xw = x @ W1a (K=128, plain)
__global__ __launch_bounds__(256) void gemm_xw_kernel(const float* __restrict__ x,
                                                      const float* __restrict__ W) {
    gemm_core<F_IN, 3, false, false>(x, W, nullptr, nullptr, g_u, nullptr);
}
// l1b: h = relu( relu(agg + b1a) @ W1b + b1b ), + stats
__global__ __launch_bounds__(256) void gemm_l1b_kernel(const float* __restrict__ W,
                                                       const float* __restrict__ bin,
                                                       const float* __restrict__ bout) {
    gemm_core<DIM, 1, true, false>(g_agg, W, bin, bout, g_h, nullptr);
}
// c: u = relu( agg @ Wp + (1+deg)*cvec + ba )
__global__ __launch_bounds__(256) void gemm_c_kernel(const float* __restrict__ ba) {
    gemm_core<DIM, 2, false, false>(g_agg, g_Wp, nullptr, ba, g_u, nullptr);
}
// d: h = relu( u @ Wb + bb ), + stats (+ pool on last layer)
template <bool POOL>
__global__ __launch_bounds__(256) void gemm_d_kernel(const float* __restrict__ W,
                                                     const float* __restrict__ bout,
                                                     const int* __restrict__ batch) {
    gemm_core<DIM, 0, true, POOL>(g_u, W, nullptr, bout, g_h, batch);
}

// ----------------------------------------------------------------------------
// Head: BN pooled sums, fc1+relu, fc2, log_softmax
// ----------------------------------------------------------------------------
__global__ void head_kernel(const float* __restrict__ fc1w, const float* __restrict__ fc1b,
                            const float* __restrict__ fc2w, const float* __restrict__ fc2b,
                            float* __restrict__ out) {
    int g = threadIdx.x;
    if (g >= G_GRAPH) return;
    float cnt = (float)g_gcnt[g];
    float p[DIM];
#pragma unroll
    for (int k = 0; k < DIM; k++)
        p[k] = fmaf(g_pooled[g * DIM + k], g_scale[k], cnt * g_shift[k]);

    float z[DIM];
#pragma unroll
    for (int j = 0; j < DIM; j++) z[j] = fc1b[j];
    for (int k = 0; k < DIM; k++) {
        float a = p[k];
#pragma unroll
        for (int j = 0; j < DIM; j++) z[j] = fmaf(a, fc1w[k * DIM + j], z[j]);
    }
#pragma unroll
    for (int j = 0; j < DIM; j++) z[j] = fmaxf(z[j], 0.f);

    float logit[C_CLS];
#pragma unroll
    for (int c = 0; c < C_CLS; c++) logit[c] = fc2b[c];
    for (int j = 0; j < DIM; j++) {
        float a = z[j];
#pragma unroll
        for (int c = 0; c < C_CLS; c++) logit[c] = fmaf(a, fc2w[j * C_CLS + c], logit[c]);
    }

    float m = logit[0];
#pragma unroll
    for (int c = 1; c < C_CLS; c++) m = fmaxf(m, logit[c]);
    float se = 0.f;
#pragma unroll
    for (int c = 0; c < C_CLS; c++) se += expf(logit[c] - m);
    float lse = m + logf(se);
#pragma unroll
    for (int c = 0; c < C_CLS; c++) out[g * C_CLS + c] = logit[c] - lse;
}

// ----------------------------------------------------------------------------
// Launch
// ----------------------------------------------------------------------------
extern "C" void kernel_launch(void* const* d_in, const int* in_sizes, int n_in,
                              void* d_out, int out_size) {
    const float* x     = (const float*)d_in[0];
    const int*   ei    = (const int*)d_in[1];
    const int*   batch = (const int*)d_in[2];
    const float* W1a = (const float*)d_in[3];
    const float* b1a = (const float*)d_in[4];
    const float* W1b = (const float*)d_in[5];
    const float* b1b = (const float*)d_in[6];
    const float* Wa  = (const float*)d_in[7];
    const float* ba  = (const float*)d_in[8];
    const float* Wb  = (const float*)d_in[9];
    const float* bb  = (const float*)d_in[10];
    const float* gammas = (const float*)d_in[11];
    const float* betas  = (const float*)d_in[12];
    const float* fc1w = (const float*)d_in[13];
    const float* fc1b = (const float*)d_in[14];
    const float* fc2w = (const float*)d_in[15];
    const float* fc2b = (const float*)d_in[16];
    float* out = (float*)d_out;

    const int TB = 256;
    const int gemm_blocks = (N_NODES + 255) / 256;            // 196
    const int gath_blocks = (N_NODES * 16 + TB - 1) / TB;     // 3125

    // CSR build + init
    init_kernel<<<(N_NODES + TB - 1) / TB, TB>>>();
    counts_kernel<<<(E_EDGES + TB - 1) / TB, TB>>>(ei, batch);
    scan_kernel<<<1, 1024>>>();
    place_kernel<<<(E_EDGES + TB - 1) / TB, TB>>>(ei);

    // ---------------- Layer 1 ----------------
    gemm_xw_kernel<<<gemm_blocks, 256>>>(x, W1a);            // g_u = x@W1a
    gather_kernel<BUF_U><<<gath_blocks, TB>>>();             // g_agg = u + sum(nbr u)
    gemm_l1b_kernel<<<gemm_blocks, 256>>>(W1b, b1a, b1b);    // g_h (+stats)
    bn_params_kernel<<<1, 64>>>(gammas, betas);
    fold_kernel<<<1, 256>>>(Wa);

    // ---------------- Layers 2..5 ----------------
    for (int L = 0; L < 4; L++) {
        gather_kernel<BUF_H><<<gath_blocks, TB>>>();
        gemm_c_kernel<<<gemm_blocks, 256>>>(ba + L * DIM);
        if (L < 3)
            gemm_d_kernel<false><<<gemm_blocks, 256>>>(Wb + L * DIM * DIM, bb + L * DIM, batch);
        else
            gemm_d_kernel<true><<<gemm_blocks, 256>>>(Wb + L * DIM * DIM, bb + L * DIM, batch);
        bn_params_kernel<<<1, 64>>>(gammas + (L + 1) * DIM, betas + (L + 1) * DIM);
        if (L < 3) fold_kernel<<<1, 256>>>(Wa + (L + 1) * DIM * DIM);
    }

    // ---------------- Head ----------------
    head_kernel<<<1, 128>>>(fc1w, fc1b, fc2w, fc2b, out);
}

// round 10
// speedup vs baseline: 1.0594x; 1.0594x over previous
#include <cuda_runtime.h>
#include <math.h>

// Problem constants
constexpr int N_NODES = 50000;
constexpr int F_IN    = 128;
constexpr int E_EDGES = 800000;
constexpr int DIM     = 64;
constexpr int G_GRAPH = 128;
constexpr int C_CLS   = 10;
constexpr float BN_EPS = 1e-5f;

// ----------------------------------------------------------------------------
// Device-global scratch (referenced ONLY from device code)
// ----------------------------------------------------------------------------
__device__ float g_agg[N_NODES * DIM];
__device__ float g_u[N_NODES * DIM];
__device__ float g_h[N_NODES * DIM];
__device__ float g_sum[DIM];
__device__ float g_sumsq[DIM];
__device__ float g_scale[DIM];
__device__ float g_shift[DIM];
__device__ float g_Wp[DIM * DIM];          // diag(scale) @ Wa_next
__device__ float g_cvec[DIM];              // shift @ Wa_next
__device__ int   g_deg[N_NODES];
__device__ int   g_gcnt[G_GRAPH];
__device__ int   g_rowstart[N_NODES + 1];
__device__ int   g_cursor[N_NODES];
__device__ int   g_csr[E_EDGES];
__device__ float g_pooled[G_GRAPH * DIM];

enum { BUF_U = 1, BUF_H = 2 };
__device__ __forceinline__ const float* get_buf(int id) {
    return id == BUF_U ? g_u : g_h;
}

__device__ __forceinline__ void red_v4(float* p, float4 v) {
    asm volatile("red.global.add.v4.f32 [%0], {%1,%2,%3,%4};"
                 :: "l"(p), "f"(v.x), "f"(v.y), "f"(v.z), "f"(v.w) : "memory");
}

// ----------------------------------------------------------------------------
// Init + CSR build
// ----------------------------------------------------------------------------
__global__ void init_kernel() {
    int t = blockIdx.x * blockDim.x + threadIdx.x;
    if (t < N_NODES) g_deg[t] = 0;
    if (t < G_GRAPH) g_gcnt[t] = 0;
    if (t < DIM) { g_sum[t] = 0.f; g_sumsq[t] = 0.f; }
    if (t < G_GRAPH * DIM) g_pooled[t] = 0.f;
}

__global__ void counts_kernel(const int* __restrict__ ei,
                              const int* __restrict__ batch) {
    int t = blockIdx.x * blockDim.x + threadIdx.x;
    if (t < E_EDGES) atomicAdd(&g_deg[ei[E_EDGES + t]], 1);
    if (t < N_NODES) atomicAdd(&g_gcnt[batch[t]], 1);
}

__global__ void scan_kernel() {
    constexpr int CH = (N_NODES + 1023) / 1024;  // 49
    int tid = threadIdx.x;
    int start = tid * CH;
    int s = 0;
    for (int i = 0; i < CH; i++) {
        int idx = start + i;
        if (idx < N_NODES) s += g_deg[idx];
    }
    __shared__ int ps[1024];
    ps[tid] = s;
    __syncthreads();
    for (int off = 1; off < 1024; off <<= 1) {
        int add = (tid >= off) ? ps[tid - off] : 0;
        __syncthreads();
        ps[tid] += add;
        __syncthreads();
    }
    int run = ps[tid] - s;   // exclusive base
    for (int i = 0; i < CH; i++) {
        int idx = start + i;
        if (idx < N_NODES) {
            g_rowstart[idx] = run;
            g_cursor[idx]   = run;
            run += g_deg[idx];
        }
    }
    if (tid == 0) g_rowstart[N_NODES] = E_EDGES;
}

__global__ void place_kernel(const int* __restrict__ ei) {
    int t = blockIdx.x * blockDim.x + threadIdx.x;
    if (t >= E_EDGES) return;
    int dst = ei[E_EDGES + t];
    int pos = atomicAdd(&g_cursor[dst], 1);
    g_csr[pos] = ei[t];
}

// ----------------------------------------------------------------------------
// bn_params (stats -> scale/shift, re-zero stats) and combined bn+fold
// ----------------------------------------------------------------------------
__global__ void bn_params_kernel(const float* __restrict__ gamma,
                                 const float* __restrict__ beta) {
    int j = threadIdx.x;
    if (j >= DIM) return;
    const float inv_n = 1.0f / (float)N_NODES;
    float mean = g_sum[j] * inv_n;
    float var  = g_sumsq[j] * inv_n - mean * mean;
    float rstd = rsqrtf(var + BN_EPS);
    float sc = gamma[j] * rstd;
    g_scale[j] = sc;
    g_shift[j] = beta[j] - mean * sc;
    g_sum[j] = 0.f;
    g_sumsq[j] = 0.f;
}

// One block of 256: compute BN params, then fold into Wa (Wp, cvec).
__global__ void bnfold_kernel(const float* __restrict__ gamma,
                              const float* __restrict__ beta,
                              const float* __restrict__ Wa) {
    __shared__ float sc_s[DIM], sh_s[DIM];
    int tid = threadIdx.x;
    if (tid < DIM) {
        const float inv_n = 1.0f / (float)N_NODES;
        float mean = g_sum[tid] * inv_n;
        float var  = g_sumsq[tid] * inv_n - mean * mean;
        float rstd = rsqrtf(var + BN_EPS);
        float sc = gamma[tid] * rstd;
        float sh = beta[tid] - mean * sc;
        sc_s[tid] = sc; sh_s[tid] = sh;
        g_scale[tid] = sc; g_shift[tid] = sh;
        g_sum[tid] = 0.f; g_sumsq[tid] = 0.f;
    }
    __syncthreads();
    for (int i = tid; i < DIM * DIM; i += 256)
        g_Wp[i] = sc_s[i >> 6] * Wa[i];
    if (tid < DIM) {
        float c = 0.f;
        for (int k = 0; k < DIM; k++) c = fmaf(sh_s[k], Wa[k * DIM + tid], c);
        g_cvec[tid] = c;
    }
}

// ----------------------------------------------------------------------------
// CSR gather: g_agg[n] = buf[n] + sum_{nbr} buf[nbr].  Half-warp per node.
// STATS: also accumulate column sum/sumsq of the SELF value (i.e. of buf)
// into g_sum/g_sumsq — each node's row is self-read exactly once here.
// Grid is exactly N_NODES*16/256 = 3125 blocks (no remainder).
// ----------------------------------------------------------------------------
template <int SRC, bool STATS>
__global__ void gather_kernel() {
    __shared__ float red1[STATS ? 16 * 65 : 1];
    __shared__ float red2[STATS ? 16 * 65 : 1];

    int tid = threadIdx.x;
    int t = blockIdx.x * 256 + tid;
    int node = t >> 4;
    int c = t & 15;
    const float4* sp = (const float4*)get_buf(SRC);

    float4 sv = sp[node * 16 + c];   // self value
    float4 acc = sv;
    int s = g_rowstart[node];
    int e = g_rowstart[node + 1];
#pragma unroll 4
    for (int j = s; j < e; j++) {
        int src = __ldg(&g_csr[j]);
        float4 v = sp[src * 16 + c];
        acc.x += v.x; acc.y += v.y; acc.z += v.z; acc.w += v.w;
    }
    ((float4*)g_agg)[node * 16 + c] = acc;

    if (STATS) {
        int nslot = tid >> 4;          // 0..15 (node slot within block)
        int col = c * 4;
        red1[nslot * 65 + col + 0] = sv.x;
        red1[nslot * 65 + col + 1] = sv.y;
        red1[nslot * 65 + col + 2] = sv.z;
        red1[nslot * 65 + col + 3] = sv.w;
        red2[nslot * 65 + col + 0] = sv.x * sv.x;
        red2[nslot * 65 + col + 1] = sv.y * sv.y;
        red2[nslot * 65 + col + 2] = sv.z * sv.z;
        red2[nslot * 65 + col + 3] = sv.w * sv.w;
        __syncthreads();
        if (tid < DIM) {
            float s1 = 0.f, s2 = 0.f;
#pragma unroll
            for (int n = 0; n < 16; n++) {
                s1 += red1[n * 65 + tid];
                s2 += red2[n * 65 + tid];
            }
            atomicAdd(&g_sum[tid], s1);
            atomicAdd(&g_sumsq[tid], s2);
        }
    }
}

// ----------------------------------------------------------------------------
// Pool of raw h by graph id, + stats of h (final layer's BN statistics)
// ----------------------------------------------------------------------------
__global__ void pool_stats_kernel(const int* __restrict__ batch) {
    __shared__ float red1[16 * 65];
    __shared__ float red2[16 * 65];

    int tid = threadIdx.x;
    int t = blockIdx.x * 256 + tid;
    int n = t >> 4;
    int c = t & 15;
    float4 v = ((const float4*)g_h)[t];
    red_v4(g_pooled + batch[n] * DIM + c * 4, v);

    int nslot = tid >> 4;
    int col = c * 4;
    red1[nslot * 65 + col + 0] = v.x;
    red1[nslot * 65 + col + 1] = v.y;
    red1[nslot * 65 + col + 2] = v.z;
    red1[nslot * 65 + col + 3] = v.w;
    red2[nslot * 65 + col + 0] = v.x * v.x;
    red2[nslot * 65 + col + 1] = v.y * v.y;
    red2[nslot * 65 + col + 2] = v.z * v.z;
    red2[nslot * 65 + col + 3] = v.w * v.w;
    __syncthreads();
    if (tid < DIM) {
        float s1 = 0.f, s2 = 0.f;
#pragma unroll
        for (int nn = 0; nn < 16; nn++) {
            s1 += red1[nn * 65 + tid];
            s2 += red2[nn * 65 + tid];
        }
        atomicAdd(&g_sum[tid], s1);
        atomicAdd(&g_sumsq[tid], s2);
    }
}

// ----------------------------------------------------------------------------
// Register-tiled GEMM core (round-6 form, known good).
// 256 threads = 64 row-threads x 4 col-groups; thread tile 4 rows x 16 cols.
// MODE: 0 = bias+relu out (d), 1 = input bias+relu too (l1b), 2 = deg*cvec (c)
// ----------------------------------------------------------------------------
template <int K, int MODE>
__device__ __forceinline__ void gemm_core(const float* __restrict__ in,
                                          const float* __restrict__ Wsrc,
                                          const float* __restrict__ bin,
                                          const float* __restrict__ bout,
                                          float* __restrict__ out) {
    __shared__ float ws[K * DIM];
    __shared__ float bi_s[DIM], bo_s[DIM], cv_s[DIM];
    int tid = threadIdx.x;
    for (int i = tid; i < K * DIM; i += 256) ws[i] = Wsrc[i];
    if (tid < DIM) {
        bo_s[tid] = bout ? bout[tid] : 0.f;
        if (MODE == 1) bi_s[tid] = bin[tid];
        if (MODE == 2) cv_s[tid] = g_cvec[tid];
    }
    __syncthreads();

    int cg = tid & 3;
    int rt = tid >> 2;
    int row0 = blockIdx.x * 256 + rt * 4;
    int colbase = cg * 16;

    float acc[4][16];
#pragma unroll
    for (int i = 0; i < 4; i++)
#pragma unroll
        for (int c = 0; c < 16; c++) acc[i][c] = 0.f;

    bool v[4];
#pragma unroll
    for (int i = 0; i < 4; i++) v[i] = (row0 + i) < N_NODES;

    const float4* in4 = (const float4*)in;
    const float4 z4 = make_float4(0.f, 0.f, 0.f, 0.f);

#pragma unroll 2
    for (int k4 = 0; k4 < K / 4; k4++) {
        float4 a[4];
#pragma unroll
        for (int i = 0; i < 4; i++)
            a[i] = v[i] ? in4[(row0 + i) * (K / 4) + k4] : z4;
        if (MODE == 1) {
            float4 b = ((const float4*)bi_s)[k4];
#pragma unroll
            for (int i = 0; i < 4; i++) {
                a[i].x = fmaxf(a[i].x + b.x, 0.f);
                a[i].y = fmaxf(a[i].y + b.y, 0.f);
                a[i].z = fmaxf(a[i].z + b.z, 0.f);
                a[i].w = fmaxf(a[i].w + b.w, 0.f);
            }
        }
#pragma unroll
        for (int kk = 0; kk < 4; kk++) {
            const float* wr = &ws[(k4 * 4 + kk) * DIM + colbase];
            float wv[16];
            *(float4*)(wv + 0)  = *(const float4*)(wr + 0);
            *(float4*)(wv + 4)  = *(const float4*)(wr + 4);
            *(float4*)(wv + 8)  = *(const float4*)(wr + 8);
            *(float4*)(wv + 12) = *(const float4*)(wr + 12);
#pragma unroll
            for (int i = 0; i < 4; i++) {
                const float* ap = (const float*)&a[i];
                float e = ap[kk];
#pragma unroll
                for (int c = 0; c < 16; c++)
                    acc[i][c] = fmaf(e, wv[c], acc[i][c]);
            }
        }
    }

    float4* o4 = (float4*)out;
#pragma unroll
    for (int i = 0; i < 4; i++) {
        if (!v[i]) continue;
        float add16[16];
        if (MODE == 2) {
            float dp1 = 1.0f + (float)g_deg[row0 + i];
#pragma unroll
            for (int c = 0; c < 16; c++)
                add16[c] = fmaf(dp1, cv_s[colbase + c], bo_s[colbase + c]);
        } else {
#pragma unroll
            for (int c = 0; c < 16; c++) add16[c] = bo_s[colbase + c];
        }
#pragma unroll
        for (int c4 = 0; c4 < 4; c4++) {
            float4 r;
            r.x = fmaxf(acc[i][4*c4+0] + add16[4*c4+0], 0.f);
            r.y = fmaxf(acc[i][4*c4+1] + add16[4*c4+1], 0.f);
            r.z = fmaxf(acc[i][4*c4+2] + add16[4*c4+2], 0.f);
            r.w = fmaxf(acc[i][4*c4+3] + add16[4*c4+3], 0.f);
            o4[(row0 + i) * 16 + cg * 4 + c4] = r;
        }
    }
}

// xw = x @ W1a (K=128, no bias/relu)
template <int K>
__global__ __launch_bounds__(256) void gemm_plain_kernel(const float* __restrict__ in,
                                                         const float* __restrict__ W) {
    __shared__ float ws[K * DIM];
    int tid = threadIdx.x;
    for (int i = tid; i < K * DIM; i += 256) ws[i] = W[i];
    __syncthreads();

    int cg = tid & 3;
    int rt = tid >> 2;
    int row0 = blockIdx.x * 256 + rt * 4;
    int colbase = cg * 16;

    float acc[4][16];
#pragma unroll
    for (int i = 0; i < 4; i++)
#pragma unroll
        for (int c = 0; c < 16; c++) acc[i][c] = 0.f;

    bool v[4];
#pragma unroll
    for (int i = 0; i < 4; i++) v[i] = (row0 + i) < N_NODES;

    const float4* in4 = (const float4*)in;
    const float4 z4 = make_float4(0.f, 0.f, 0.f, 0.f);

#pragma unroll 2
    for (int k4 = 0; k4 < K / 4; k4++) {
        float4 a[4];
#pragma unroll
        for (int i = 0; i < 4; i++)
            a[i] = v[i] ? in4[(row0 + i) * (K / 4) + k4] : z4;
#pragma unroll
        for (int kk = 0; kk < 4; kk++) {
            const float* wr = &ws[(k4 * 4 + kk) * DIM + colbase];
            float wv[16];
            *(float4*)(wv + 0)  = *(const float4*)(wr + 0);
            *(float4*)(wv + 4)  = *(const float4*)(wr + 4);
            *(float4*)(wv + 8)  = *(const float4*)(wr + 8);
            *(float4*)(wv + 12) = *(const float4*)(wr + 12);
#pragma unroll
            for (int i = 0; i < 4; i++) {
                const float* ap = (const float*)&a[i];
                float e = ap[kk];
#pragma unroll
                for (int c = 0; c < 16; c++)
                    acc[i][c] = fmaf(e, wv[c], acc[i][c]);
            }
        }
    }

    float4* o4 = (float4*)g_u;
#pragma unroll
    for (int i = 0; i < 4; i++) {
        if (!v[i]) continue;
#pragma unroll
        for (int c4 = 0; c4 < 4; c4++) {
            float4 r = make_float4(acc[i][4*c4+0], acc[i][4*c4+1],
                                   acc[i][4*c4+2], acc[i][4*c4+3]);
            o4[(row0 + i) * 16 + cg * 4 + c4] = r;
        }
    }
}

// l1b: h = relu( relu(agg + b1a) @ W1b + b1b )
__global__ __launch_bounds__(256) void gemm_l1b_kernel(const float* __restrict__ W,
                                                       const float* __restrict__ bin,
                                                       const float* __restrict__ bout) {
    gemm_core<DIM, 1>(g_agg, W, bin, bout, g_h);
}
// c: u = relu( agg @ Wp + (1+deg)*cvec + ba )
__global__ __launch_bounds__(256) void gemm_c_kernel(const float* __restrict__ ba) {
    gemm_core<DIM, 2>(g_agg, g_Wp, nullptr, ba, g_u);
}
// d: h = relu( u @ Wb + bb )
__global__ __launch_bounds__(256) void gemm_d_kernel(const float* __restrict__ W,
                                                     const float* __restrict__ bout) {
    gemm_core<DIM, 0>(g_u, W, nullptr, bout, g_h);
}

// ----------------------------------------------------------------------------
// Head
// ----------------------------------------------------------------------------
__global__ void head_kernel(const float* __restrict__ fc1w, const float* __restrict__ fc1b,
                            const float* __restrict__ fc2w, const float* __restrict__ fc2b,
                            float* __restrict__ out) {
    int g = threadIdx.x;
    if (g >= G_GRAPH) return;
    float cnt = (float)g_gcnt[g];
    float p[DIM];
#pragma unroll
    for (int k = 0; k < DIM; k++)
        p[k] = fmaf(g_pooled[g * DIM + k], g_scale[k], cnt * g_shift[k]);

    float z[DIM];
#pragma unroll
    for (int j = 0; j < DIM; j++) z[j] = fc1b[j];
    for (int k = 0; k < DIM; k++) {
        float a = p[k];
#pragma unroll
        for (int j = 0; j < DIM; j++) z[j] = fmaf(a, fc1w[k * DIM + j], z[j]);
    }
#pragma unroll
    for (int j = 0; j < DIM; j++) z[j] = fmaxf(z[j], 0.f);

    float logit[C_CLS];
#pragma unroll
    for (int c = 0; c < C_CLS; c++) logit[c] = fc2b[c];
    for (int j = 0; j < DIM; j++) {
        float a = z[j];
#pragma unroll
        for (int c = 0; c < C_CLS; c++) logit[c] = fmaf(a, fc2w[j * C_CLS + c], logit[c]);
    }

    float m = logit[0];
#pragma unroll
    for (int c = 1; c < C_CLS; c++) m = fmaxf(m, logit[c]);
    float se = 0.f;
#pragma unroll
    for (int c = 0; c < C_CLS; c++) se += expf(logit[c] - m);
    float lse = m + logf(se);
#pragma unroll
    for (int c = 0; c < C_CLS; c++) out[g * C_CLS + c] = logit[c] - lse;
}

// ----------------------------------------------------------------------------
// Launch
// ----------------------------------------------------------------------------
extern "C" void kernel_launch(void* const* d_in, const int* in_sizes, int n_in,
                              void* d_out, int out_size) {
    const float* x     = (const float*)d_in[0];
    const int*   ei    = (const int*)d_in[1];
    const int*   batch = (const int*)d_in[2];
    const float* W1a = (const float*)d_in[3];
    const float* b1a = (const float*)d_in[4];
    const float* W1b = (const float*)d_in[5];
    const float* b1b = (const float*)d_in[6];
    const float* Wa  = (const float*)d_in[7];
    const float* ba  = (const float*)d_in[8];
    const float* Wb  = (const float*)d_in[9];
    const float* bb  = (const float*)d_in[10];
    const float* gammas = (const float*)d_in[11];
    const float* betas  = (const float*)d_in[12];
    const float* fc1w = (const float*)d_in[13];
    const float* fc1b = (const float*)d_in[14];
    const float* fc2w = (const float*)d_in[15];
    const float* fc2b = (const float*)d_in[16];
    float* out = (float*)d_out;

    const int TB = 256;
    const int gemm_blocks = (N_NODES + 255) / 256;            // 196
    const int gath_blocks = (N_NODES * 16) / TB;              // 3125 exact

    // CSR build + init
    init_kernel<<<(N_NODES + TB - 1) / TB, TB>>>();
    counts_kernel<<<(E_EDGES + TB - 1) / TB, TB>>>(ei, batch);
    scan_kernel<<<1, 1024>>>();
    place_kernel<<<(E_EDGES + TB - 1) / TB, TB>>>(ei);

    // ---------------- Layer 1 ----------------
    gemm_plain_kernel<F_IN><<<gemm_blocks, 256>>>(x, W1a);   // g_u = x@W1a
    gather_kernel<BUF_U, false><<<gath_blocks, TB>>>();       // g_agg = u + sum(nbr u)
    gemm_l1b_kernel<<<gemm_blocks, 256>>>(W1b, b1a, b1b);     // g_h

    // ---------------- Layers 2..5 ----------------
    for (int L = 0; L < 4; L++) {
        // gather h for this conv; piggyback stats of h (prev layer's BN)
        gather_kernel<BUF_H, true><<<gath_blocks, TB>>>();
        // BN params of prev layer + fold into Wa[L]
        bnfold_kernel<<<1, 256>>>(gammas + L * DIM, betas + L * DIM,
                                  Wa + L * DIM * DIM);
        gemm_c_kernel<<<gemm_blocks, 256>>>(ba + L * DIM);
        gemm_d_kernel<<<gemm_blocks, 256>>>(Wb + L * DIM * DIM, bb + L * DIM);
    }

    // ---------------- Pool (+final stats) + head ----------------
    pool_stats_kernel<<<gath_blocks, TB>>>(batch);
    bn_params_kernel<<<1, 64>>>(gammas + 4 * DIM, betas + 4 * DIM);
    head_kernel<<<1, 128>>>(fc1w, fc1b, fc2w, fc2b, out);
}

// round 11
// speedup vs baseline: 1.0611x; 1.0016x over previous
#include <cuda_runtime.h>
#include <math.h>

// Problem constants
constexpr int N_NODES = 50000;
constexpr int F_IN    = 128;
constexpr int E_EDGES = 800000;
constexpr int DIM     = 64;
constexpr int G_GRAPH = 128;
constexpr int C_CLS   = 10;
constexpr float BN_EPS = 1e-5f;

// ----------------------------------------------------------------------------
// Device-global scratch (referenced ONLY from device code)
// ----------------------------------------------------------------------------
__device__ float g_agg[N_NODES * DIM];
__device__ float g_u[N_NODES * DIM];
__device__ float g_h[N_NODES * DIM];
__device__ float g_sum[DIM];
__device__ float g_sumsq[DIM];
__device__ float g_scale[DIM];
__device__ float g_shift[DIM];
__device__ float g_Wp[DIM * DIM];          // diag(scale) @ Wa_next
__device__ float g_cvec[DIM];              // shift @ Wa_next
__device__ int   g_deg[N_NODES];
__device__ int   g_gcnt[G_GRAPH];
__device__ int   g_rowstart[N_NODES + 1];
__device__ int   g_cursor[N_NODES];
__device__ int   g_csr[E_EDGES];
__device__ float g_pooled[G_GRAPH * DIM];

enum { BUF_U = 1, BUF_H = 2 };
__device__ __forceinline__ const float* get_buf(int id) {
    return id == BUF_U ? g_u : g_h;
}

__device__ __forceinline__ void red_v4(float* p, float4 v) {
    asm volatile("red.global.add.v4.f32 [%0], {%1,%2,%3,%4};"
                 :: "l"(p), "f"(v.x), "f"(v.y), "f"(v.z), "f"(v.w) : "memory");
}

// ----------------------------------------------------------------------------
// Init + CSR build (runs on side stream, overlapped with gemm_xw)
// ----------------------------------------------------------------------------
__global__ void init_kernel() {
    int t = blockIdx.x * blockDim.x + threadIdx.x;
    if (t < N_NODES) g_deg[t] = 0;
    if (t < G_GRAPH) g_gcnt[t] = 0;
    if (t < DIM) { g_sum[t] = 0.f; g_sumsq[t] = 0.f; }
    if (t < G_GRAPH * DIM) g_pooled[t] = 0.f;
}

__global__ void counts_kernel(const int* __restrict__ ei,
                              const int* __restrict__ batch) {
    int t = blockIdx.x * blockDim.x + threadIdx.x;
    if (t < E_EDGES) atomicAdd(&g_deg[ei[E_EDGES + t]], 1);
    if (t < N_NODES) atomicAdd(&g_gcnt[batch[t]], 1);
}

__global__ void scan_kernel() {
    constexpr int CH = (N_NODES + 1023) / 1024;  // 49
    int tid = threadIdx.x;
    int start = tid * CH;
    int s = 0;
    for (int i = 0; i < CH; i++) {
        int idx = start + i;
        if (idx < N_NODES) s += g_deg[idx];
    }
    __shared__ int ps[1024];
    ps[tid] = s;
    __syncthreads();
    for (int off = 1; off < 1024; off <<= 1) {
        int add = (tid >= off) ? ps[tid - off] : 0;
        __syncthreads();
        ps[tid] += add;
        __syncthreads();
    }
    int run = ps[tid] - s;   // exclusive base
    for (int i = 0; i < CH; i++) {
        int idx = start + i;
        if (idx < N_NODES) {
            g_rowstart[idx] = run;
            g_cursor[idx]   = run;
            run += g_deg[idx];
        }
    }
    if (tid == 0) g_rowstart[N_NODES] = E_EDGES;
}

__global__ void place_kernel(const int* __restrict__ ei) {
    int t = blockIdx.x * blockDim.x + threadIdx.x;
    if (t >= E_EDGES) return;
    int dst = ei[E_EDGES + t];
    int pos = atomicAdd(&g_cursor[dst], 1);
    g_csr[pos] = ei[t];
}

// ----------------------------------------------------------------------------
// BN params + fold into Wa (Wp, cvec). One block of 256.
// ----------------------------------------------------------------------------
__global__ void bnfold_kernel(const float* __restrict__ gamma,
                              const float* __restrict__ beta,
                              const float* __restrict__ Wa) {
    __shared__ float sc_s[DIM], sh_s[DIM];
    int tid = threadIdx.x;
    if (tid < DIM) {
        const float inv_n = 1.0f / (float)N_NODES;
        float mean = g_sum[tid] * inv_n;
        float var  = g_sumsq[tid] * inv_n - mean * mean;
        float rstd = rsqrtf(var + BN_EPS);
        float sc = gamma[tid] * rstd;
        float sh = beta[tid] - mean * sc;
        sc_s[tid] = sc; sh_s[tid] = sh;
        g_scale[tid] = sc; g_shift[tid] = sh;
        g_sum[tid] = 0.f; g_sumsq[tid] = 0.f;
    }
    __syncthreads();
    for (int i = tid; i < DIM * DIM; i += 256)
        g_Wp[i] = sc_s[i >> 6] * Wa[i];
    if (tid < DIM) {
        float c = 0.f;
        for (int k = 0; k < DIM; k++) c = fmaf(sh_s[k], Wa[k * DIM + tid], c);
        g_cvec[tid] = c;
    }
}

// ----------------------------------------------------------------------------
// CSR gather: g_agg[n] = buf[n] + sum_{nbr} buf[nbr].  Half-warp per node.
// STATS: piggyback column sum/sumsq of the SELF value into g_sum/g_sumsq.
// ----------------------------------------------------------------------------
template <int SRC, bool STATS>
__global__ void gather_kernel() {
    __shared__ float red1[STATS ? 16 * 65 : 1];
    __shared__ float red2[STATS ? 16 * 65 : 1];

    int tid = threadIdx.x;
    int t = blockIdx.x * 256 + tid;
    int node = t >> 4;
    int c = t & 15;
    const float4* sp = (const float4*)get_buf(SRC);

    float4 sv = sp[node * 16 + c];   // self value
    float4 acc = sv;
    int s = g_rowstart[node];
    int e = g_rowstart[node + 1];
#pragma unroll 4
    for (int j = s; j < e; j++) {
        int src = __ldg(&g_csr[j]);
        float4 v = sp[src * 16 + c];
        acc.x += v.x; acc.y += v.y; acc.z += v.z; acc.w += v.w;
    }
    ((float4*)g_agg)[node * 16 + c] = acc;

    if (STATS) {
        int nslot = tid >> 4;
        int col = c * 4;
        red1[nslot * 65 + col + 0] = sv.x;
        red1[nslot * 65 + col + 1] = sv.y;
        red1[nslot * 65 + col + 2] = sv.z;
        red1[nslot * 65 + col + 3] = sv.w;
        red2[nslot * 65 + col + 0] = sv.x * sv.x;
        red2[nslot * 65 + col + 1] = sv.y * sv.y;
        red2[nslot * 65 + col + 2] = sv.z * sv.z;
        red2[nslot * 65 + col + 3] = sv.w * sv.w;
        __syncthreads();
        if (tid < DIM) {
            float s1 = 0.f, s2 = 0.f;
#pragma unroll
            for (int n = 0; n < 16; n++) {
                s1 += red1[n * 65 + tid];
                s2 += red2[n * 65 + tid];
            }
            atomicAdd(&g_sum[tid], s1);
            atomicAdd(&g_sumsq[tid], s2);
        }
    }
}

// ----------------------------------------------------------------------------
// Pool of raw h by graph id, + stats of h (final layer's BN statistics)
// ----------------------------------------------------------------------------
__global__ void pool_stats_kernel(const int* __restrict__ batch) {
    __shared__ float red1[16 * 65];
    __shared__ float red2[16 * 65];

    int tid = threadIdx.x;
    int t = blockIdx.x * 256 + tid;
    int n = t >> 4;
    int c = t & 15;
    float4 v = ((const float4*)g_h)[t];
    red_v4(g_pooled + batch[n] * DIM + c * 4, v);

    int nslot = tid >> 4;
    int col = c * 4;
    red1[nslot * 65 + col + 0] = v.x;
    red1[nslot * 65 + col + 1] = v.y;
    red1[nslot * 65 + col + 2] = v.z;
    red1[nslot * 65 + col + 3] = v.w;
    red2[nslot * 65 + col + 0] = v.x * v.x;
    red2[nslot * 65 + col + 1] = v.y * v.y;
    red2[nslot * 65 + col + 2] = v.z * v.z;
    red2[nslot * 65 + col + 3] = v.w * v.w;
    __syncthreads();
    if (tid < DIM) {
        float s1 = 0.f, s2 = 0.f;
#pragma unroll
        for (int nn = 0; nn < 16; nn++) {
            s1 += red1[nn * 65 + tid];
            s2 += red2[nn * 65 + tid];
        }
        atomicAdd(&g_sum[tid], s1);
        atomicAdd(&g_sumsq[tid], s2);
    }
}

// ----------------------------------------------------------------------------
// gemm_plain: g_u = in @ W (no bias/relu). Round-6 proven tiling:
// 256 threads = 64 row-threads x 4 col-groups; thread tile 4 rows x 16 cols.
// ----------------------------------------------------------------------------
template <int K>
__global__ __launch_bounds__(256) void gemm_plain_kernel(const float* __restrict__ in,
                                                         const float* __restrict__ W) {
    __shared__ float ws[K * DIM];
    int tid = threadIdx.x;
    for (int i = tid; i < K * DIM; i += 256) ws[i] = W[i];
    __syncthreads();

    int cg = tid & 3;
    int rt = tid >> 2;
    int row0 = blockIdx.x * 256 + rt * 4;
    int colbase = cg * 16;

    float acc[4][16];
#pragma unroll
    for (int i = 0; i < 4; i++)
#pragma unroll
        for (int c = 0; c < 16; c++) acc[i][c] = 0.f;

    bool v[4];
#pragma unroll
    for (int i = 0; i < 4; i++) v[i] = (row0 + i) < N_NODES;

    const float4* in4 = (const float4*)in;
    const float4 z4 = make_float4(0.f, 0.f, 0.f, 0.f);

#pragma unroll 2
    for (int k4 = 0; k4 < K / 4; k4++) {
        float4 a[4];
#pragma unroll
        for (int i = 0; i < 4; i++)
            a[i] = v[i] ? in4[(row0 + i) * (K / 4) + k4] : z4;
#pragma unroll
        for (int kk = 0; kk < 4; kk++) {
            const float* wr = &ws[(k4 * 4 + kk) * DIM + colbase];
            float wv[16];
            *(float4*)(wv + 0)  = *(const float4*)(wr + 0);
            *(float4*)(wv + 4)  = *(const float4*)(wr + 4);
            *(float4*)(wv + 8)  = *(const float4*)(wr + 8);
            *(float4*)(wv + 12) = *(const float4*)(wr + 12);
#pragma unroll
            for (int i = 0; i < 4; i++) {
                const float* ap = (const float*)&a[i];
                float e = ap[kk];
#pragma unroll
                for (int c = 0; c < 16; c++)
                    acc[i][c] = fmaf(e, wv[c], acc[i][c]);
            }
        }
    }

    float4* o4 = (float4*)g_u;
#pragma unroll
    for (int i = 0; i < 4; i++) {
        if (!v[i]) continue;
#pragma unroll
        for (int c4 = 0; c4 < 4; c4++) {
            float4 r = make_float4(acc[i][4*c4+0], acc[i][4*c4+1],
                                   acc[i][4*c4+2], acc[i][4*c4+3]);
            o4[(row0 + i) * 16 + cg * 4 + c4] = r;
        }
    }
}

// ----------------------------------------------------------------------------
// l1b: h = relu( relu(agg + b1a) @ W1b + b1b )  (round-6 tiling)
// ----------------------------------------------------------------------------
__global__ __launch_bounds__(256) void gemm_l1b_kernel(const float* __restrict__ W,
                                                       const float* __restrict__ bin,
                                                       const float* __restrict__ bout) {
    __shared__ float ws[DIM * DIM];
    __shared__ float bi_s[DIM], bo_s[DIM];
    int tid = threadIdx.x;
    for (int i = tid; i < DIM * DIM; i += 256) ws[i] = W[i];
    if (tid < DIM) { bi_s[tid] = bin[tid]; bo_s[tid] = bout[tid]; }
    __syncthreads();

    int cg = tid & 3;
    int rt = tid >> 2;
    int row0 = blockIdx.x * 256 + rt * 4;
    int colbase = cg * 16;

    float acc[4][16];
#pragma unroll
    for (int i = 0; i < 4; i++)
#pragma unroll
        for (int c = 0; c < 16; c++) acc[i][c] = 0.f;

    bool v[4];
#pragma unroll
    for (int i = 0; i < 4; i++) v[i] = (row0 + i) < N_NODES;

    const float4* in4 = (const float4*)g_agg;
    const float4 z4 = make_float4(0.f, 0.f, 0.f, 0.f);

#pragma unroll 2
    for (int k4 = 0; k4 < DIM / 4; k4++) {
        float4 a[4];
#pragma unroll
        for (int i = 0; i < 4; i++)
            a[i] = v[i] ? in4[(row0 + i) * 16 + k4] : z4;
        float4 b = ((const float4*)bi_s)[k4];
#pragma unroll
        for (int i = 0; i < 4; i++) {
            a[i].x = fmaxf(a[i].x + b.x, 0.f);
            a[i].y = fmaxf(a[i].y + b.y, 0.f);
            a[i].z = fmaxf(a[i].z + b.z, 0.f);
            a[i].w = fmaxf(a[i].w + b.w, 0.f);
        }
#pragma unroll
        for (int kk = 0; kk < 4; kk++) {
            const float* wr = &ws[(k4 * 4 + kk) * DIM + colbase];
            float wv[16];
            *(float4*)(wv + 0)  = *(const float4*)(wr + 0);
            *(float4*)(wv + 4)  = *(const float4*)(wr + 4);
            *(float4*)(wv + 8)  = *(const float4*)(wr + 8);
            *(float4*)(wv + 12) = *(const float4*)(wr + 12);
#pragma unroll
            for (int i = 0; i < 4; i++) {
                const float* ap = (const float*)&a[i];
                float e = ap[kk];
#pragma unroll
                for (int c = 0; c < 16; c++)
                    acc[i][c] = fmaf(e, wv[c], acc[i][c]);
            }
        }
    }

    float4* o4 = (float4*)g_h;
#pragma unroll
    for (int i = 0; i < 4; i++) {
        if (!v[i]) continue;
#pragma unroll
        for (int c4 = 0; c4 < 4; c4++) {
            float4 r;
            r.x = fmaxf(acc[i][4*c4+0] + bo_s[colbase + 4*c4+0], 0.f);
            r.y = fmaxf(acc[i][4*c4+1] + bo_s[colbase + 4*c4+1], 0.f);
            r.z = fmaxf(acc[i][4*c4+2] + bo_s[colbase + 4*c4+2], 0.f);
            r.w = fmaxf(acc[i][4*c4+3] + bo_s[colbase + 4*c4+3], 0.f);
            o4[(row0 + i) * 16 + cg * 4 + c4] = r;
        }
    }
}

// ----------------------------------------------------------------------------
// Fused conv MLP for layers 2..5:
//   u = relu( agg @ Wp + (1+deg)*cvec + ba )    [phase 1, in registers]
//   h = relu( u @ Wb + bb )                     [phase 2, u exchanged via shfl]
// 256 threads = 64 row-threads x 4 col-groups; thread tile 2 rows x 16 cols.
// Block tile 128 rows. u never touches memory.
// ----------------------------------------------------------------------------
__global__ __launch_bounds__(256) void gemm_cd_kernel(const float* __restrict__ ba_p,
                                                      const float* __restrict__ Wb,
                                                      const float* __restrict__ bb_p) {
    __shared__ float wsa[DIM * DIM];
    __shared__ float wsb[DIM * DIM];
    __shared__ float cv_s[DIM], ba_s[DIM], bb_s[DIM];
    int tid = threadIdx.x;
    for (int i = tid; i < DIM * DIM; i += 256) { wsa[i] = g_Wp[i]; wsb[i] = Wb[i]; }
    if (tid < DIM) { cv_s[tid] = g_cvec[tid]; ba_s[tid] = ba_p[tid]; bb_s[tid] = bb_p[tid]; }
    __syncthreads();

    int cg = tid & 3;
    int rt = tid >> 2;                 // 0..63
    int row0 = blockIdx.x * 128 + rt * 2;
    int colbase = cg * 16;
    int lane = tid & 31;

    bool v[2];
    v[0] = (row0 + 0) < N_NODES;
    v[1] = (row0 + 1) < N_NODES;

    const float4 z4 = make_float4(0.f, 0.f, 0.f, 0.f);
    const float4* in4 = (const float4*)g_agg;

    // ---- Phase 1: u = agg @ Wp ----
    float ua[2][16];
#pragma unroll
    for (int i = 0; i < 2; i++)
#pragma unroll
        for (int c = 0; c < 16; c++) ua[i][c] = 0.f;

#pragma unroll 2
    for (int k4 = 0; k4 < 16; k4++) {
        float4 a[2];
        a[0] = v[0] ? in4[(row0 + 0) * 16 + k4] : z4;
        a[1] = v[1] ? in4[(row0 + 1) * 16 + k4] : z4;
#pragma unroll
        for (int kk = 0; kk < 4; kk++) {
            const float* wr = &wsa[(k4 * 4 + kk) * DIM + colbase];
            float wv[16];
            *(float4*)(wv + 0)  = *(const float4*)(wr + 0);
            *(float4*)(wv + 4)  = *(const float4*)(wr + 4);
            *(float4*)(wv + 8)  = *(const float4*)(wr + 8);
            *(float4*)(wv + 12) = *(const float4*)(wr + 12);
#pragma unroll
            for (int i = 0; i < 2; i++) {
                const float* ap = (const float*)&a[i];
                float e = ap[kk];
#pragma unroll
                for (int c = 0; c < 16; c++)
                    ua[i][c] = fmaf(e, wv[c], ua[i][c]);
            }
        }
    }

    // epilogue of phase 1: (1+deg)*cvec + ba, relu
#pragma unroll
    for (int i = 0; i < 2; i++) {
        float dp1 = v[i] ? 1.0f + (float)g_deg[row0 + i] : 0.f;
#pragma unroll
        for (int c = 0; c < 16; c++)
            ua[i][c] = fmaxf(fmaf(dp1, cv_s[colbase + c], ua[i][c]) + ba_s[colbase + c], 0.f);
    }

    // ---- Phase 2: h = u @ Wb (u exchanged across col-groups via shfl) ----
    float ha[2][16];
#pragma unroll
    for (int i = 0; i < 2; i++)
#pragma unroll
        for (int c = 0; c < 16; c++) ha[i][c] = 0.f;

#pragma unroll 1
    for (int src = 0; src < 4; src++) {
        int srclane = (lane & ~3) | src;
#pragma unroll
        for (int kk = 0; kk < 16; kk++) {
            int k = src * 16 + kk;
            float e0 = __shfl_sync(0xffffffffu, ua[0][kk], srclane);
            float e1 = __shfl_sync(0xffffffffu, ua[1][kk], srclane);
            const float* wr = &wsb[k * DIM + colbase];
            float wv[16];
            *(float4*)(wv + 0)  = *(const float4*)(wr + 0);
            *(float4*)(wv + 4)  = *(const float4*)(wr + 4);
            *(float4*)(wv + 8)  = *(const float4*)(wr + 8);
            *(float4*)(wv + 12) = *(const float4*)(wr + 12);
#pragma unroll
            for (int c = 0; c < 16; c++) {
                ha[0][c] = fmaf(e0, wv[c], ha[0][c]);
                ha[1][c] = fmaf(e1, wv[c], ha[1][c]);
            }
        }
    }

    float4* o4 = (float4*)g_h;
#pragma unroll
    for (int i = 0; i < 2; i++) {
        if (!v[i]) continue;
#pragma unroll
        for (int c4 = 0; c4 < 4; c4++) {
            float4 r;
            r.x = fmaxf(ha[i][4*c4+0] + bb_s[colbase + 4*c4+0], 0.f);
            r.y = fmaxf(ha[i][4*c4+1] + bb_s[colbase + 4*c4+1], 0.f);
            r.z = fmaxf(ha[i][4*c4+2] + bb_s[colbase + 4*c4+2], 0.f);
            r.w = fmaxf(ha[i][4*c4+3] + bb_s[colbase + 4*c4+3], 0.f);
            o4[(row0 + i) * 16 + cg * 4 + c4] = r;
        }
    }
}

// ----------------------------------------------------------------------------
// Head: compute final BN params from stats, BN pooled sums, fc1+relu, fc2,
// log_softmax. One block of 128.
// ----------------------------------------------------------------------------
__global__ void head_kernel(const float* __restrict__ gamma, const float* __restrict__ beta,
                            const float* __restrict__ fc1w, const float* __restrict__ fc1b,
                            const float* __restrict__ fc2w, const float* __restrict__ fc2b,
                            float* __restrict__ out) {
    __shared__ float sc_s[DIM], sh_s[DIM];
    int g = threadIdx.x;
    if (g < DIM) {
        const float inv_n = 1.0f / (float)N_NODES;
        float mean = g_sum[g] * inv_n;
        float var  = g_sumsq[g] * inv_n - mean * mean;
        float rstd = rsqrtf(var + BN_EPS);
        float sc = gamma[g] * rstd;
        sc_s[g] = sc;
        sh_s[g] = beta[g] - mean * sc;
    }
    __syncthreads();
    if (g >= G_GRAPH) return;

    float cnt = (float)g_gcnt[g];
    float p[DIM];
#pragma unroll
    for (int k = 0; k < DIM; k++)
        p[k] = fmaf(g_pooled[g * DIM + k], sc_s[k], cnt * sh_s[k]);

    float z[DIM];
#pragma unroll
    for (int j = 0; j < DIM; j++) z[j] = fc1b[j];
    for (int k = 0; k < DIM; k++) {
        float a = p[k];
#pragma unroll
        for (int j = 0; j < DIM; j++) z[j] = fmaf(a, fc1w[k * DIM + j], z[j]);
    }
#pragma unroll
    for (int j = 0; j < DIM; j++) z[j] = fmaxf(z[j], 0.f);

    float logit[C_CLS];
#pragma unroll
    for (int c = 0; c < C_CLS; c++) logit[c] = fc2b[c];
    for (int j = 0; j < DIM; j++) {
        float a = z[j];
#pragma unroll
        for (int c = 0; c < C_CLS; c++) logit[c] = fmaf(a, fc2w[j * C_CLS + c], logit[c]);
    }

    float m = logit[0];
#pragma unroll
    for (int c = 1; c < C_CLS; c++) m = fmaxf(m, logit[c]);
    float se = 0.f;
#pragma unroll
    for (int c = 0; c < C_CLS; c++) se += expf(logit[c] - m);
    float lse = m + logf(se);
#pragma unroll
    for (int c = 0; c < C_CLS; c++) out[g * C_CLS + c] = logit[c] - lse;
}

// ----------------------------------------------------------------------------
// Launch — CSR build forked onto side stream, overlapped with gemm_xw
// ----------------------------------------------------------------------------
extern "C" void kernel_launch(void* const* d_in, const int* in_sizes, int n_in,
                              void* d_out, int out_size) {
    const float* x     = (const float*)d_in[0];
    const int*   ei    = (const int*)d_in[1];
    const int*   batch = (const int*)d_in[2];
    const float* W1a = (const float*)d_in[3];
    const float* b1a = (const float*)d_in[4];
    const float* W1b = (const float*)d_in[5];
    const float* b1b = (const float*)d_in[6];
    const float* Wa  = (const float*)d_in[7];
    const float* ba  = (const float*)d_in[8];
    const float* Wb  = (const float*)d_in[9];
    const float* bb  = (const float*)d_in[10];
    const float* gammas = (const float*)d_in[11];
    const float* betas  = (const float*)d_in[12];
    const float* fc1w = (const float*)d_in[13];
    const float* fc1b = (const float*)d_in[14];
    const float* fc2w = (const float*)d_in[15];
    const float* fc2b = (const float*)d_in[16];
    float* out = (float*)d_out;

    // Lazily created once on the (uncaptured) correctness call; reused in capture.
    static cudaStream_t s2 = nullptr;
    static cudaEvent_t ev_fork = nullptr, ev_join = nullptr;
    if (s2 == nullptr) {
        cudaStreamCreateWithFlags(&s2, cudaStreamNonBlocking);
        cudaEventCreateWithFlags(&ev_fork, cudaEventDisableTiming);
        cudaEventCreateWithFlags(&ev_join, cudaEventDisableTiming);
    }

    const int TB = 256;
    const int gemm_blocks = (N_NODES + 255) / 256;            // 196
    const int cd_blocks   = (N_NODES + 127) / 128;            // 391
    const int gath_blocks = (N_NODES * 16) / TB;              // 3125 exact
    const int edge_blocks = (E_EDGES + TB - 1) / TB;          // 3125

    // ---- fork: CSR build + init on s2, xw on main ----
    cudaEventRecord(ev_fork, 0);
    cudaStreamWaitEvent(s2, ev_fork, 0);
    init_kernel<<<gemm_blocks, TB, 0, s2>>>();
    counts_kernel<<<edge_blocks, TB, 0, s2>>>(ei, batch);
    scan_kernel<<<1, 1024, 0, s2>>>();
    place_kernel<<<edge_blocks, TB, 0, s2>>>(ei);
    cudaEventRecord(ev_join, s2);

    gemm_plain_kernel<F_IN><<<gemm_blocks, 256>>>(x, W1a);    // g_u = x@W1a
    cudaStreamWaitEvent(0, ev_join, 0);                       // join

    // ---------------- Layer 1 ----------------
    gather_kernel<BUF_U, false><<<gath_blocks, TB>>>();       // g_agg = u + sum(nbr u)
    gemm_l1b_kernel<<<gemm_blocks, 256>>>(W1b, b1a, b1b);     // g_h

    // ---------------- Layers 2..5 ----------------
    for (int L = 0; L < 4; L++) {
        gather_kernel<BUF_H, true><<<gath_blocks, TB>>>();    // + stats of h
        bnfold_kernel<<<1, 256>>>(gammas + L * DIM, betas + L * DIM,
                                  Wa + L * DIM * DIM);
        gemm_cd_kernel<<<cd_blocks, 256>>>(ba + L * DIM,
                                           Wb + L * DIM * DIM, bb + L * DIM);
    }

    // ---------------- Pool (+final stats) + head ----------------
    pool_stats_kernel<<<gath_blocks, TB>>>(batch);
    head_kernel<<<1, 128>>>(gammas + 4 * DIM, betas + 4 * DIM,
                            fc1w, fc1b, fc2w, fc2b, out);
}